// round 1
// baseline (speedup 1.0000x reference)
#include <cuda_runtime.h>
#include <math.h>

#define SOM_DIM   512
#define SOM_MN    65536          // 256*256 rows
#define ROWS_PER_BLK 8           // 8 warps per block, one row per warp
#define N_BLOCKS_P1 (SOM_MN / ROWS_PER_BLK)   // 8192

__device__ unsigned long long g_partial[N_BLOCKS_P1];
__device__ int g_bmu_idx;

// ---------------------------------------------------------------------------
// Pass 1: per-row squared distance (matches argmin of sqrt since sqrt is
// monotonic). One warp per row; 4x float4 loads per lane (MLP=4, coalesced).
// Block-level min of packed (dist_bits<<32 | row) keys -> g_partial[block].
// ---------------------------------------------------------------------------
__global__ __launch_bounds__(256) void som_dist_kernel(
    const float* __restrict__ x, const float* __restrict__ w)
{
    __shared__ unsigned long long s_keys[ROWS_PER_BLK];
    const int lane = threadIdx.x & 31;
    const int warp = threadIdx.x >> 5;
    const int row  = blockIdx.x * ROWS_PER_BLK + warp;

    const float4* __restrict__ wr = (const float4*)(w + (size_t)row * SOM_DIM);
    const float4* __restrict__ xr = (const float4*)x;

    float acc = 0.0f;
#pragma unroll
    for (int i = 0; i < 4; i++) {
        const int idx = lane + i * 32;            // 128 float4 per row
        float4 wv = wr[idx];
        float4 xv = __ldg(&xr[idx]);
        float d0 = xv.x - wv.x + 1e-6f;
        float d1 = xv.y - wv.y + 1e-6f;
        float d2 = xv.z - wv.z + 1e-6f;
        float d3 = xv.w - wv.w + 1e-6f;
        acc += d0*d0 + d1*d1 + d2*d2 + d3*d3;
    }
#pragma unroll
    for (int o = 16; o > 0; o >>= 1)
        acc += __shfl_xor_sync(0xFFFFFFFFu, acc, o);

    if (lane == 0) {
        // acc >= 0 so fp32 bit pattern is order-preserving as uint.
        unsigned long long key =
            ((unsigned long long)__float_as_uint(acc) << 32) | (unsigned)row;
        s_keys[warp] = key;
    }
    __syncthreads();
    if (threadIdx.x == 0) {
        unsigned long long k = s_keys[0];
#pragma unroll
        for (int i = 1; i < ROWS_PER_BLK; i++)
            k = min(k, s_keys[i]);
        g_partial[blockIdx.x] = k;
    }
}

// ---------------------------------------------------------------------------
// Pass 1b: deterministic reduction of 8192 partial keys -> g_bmu_idx.
// ---------------------------------------------------------------------------
__global__ __launch_bounds__(1024) void som_reduce_kernel()
{
    __shared__ unsigned long long sk[1024];
    unsigned long long k = 0xFFFFFFFFFFFFFFFFULL;
    for (int i = threadIdx.x; i < N_BLOCKS_P1; i += 1024)
        k = min(k, g_partial[i]);
    sk[threadIdx.x] = k;
    __syncthreads();
#pragma unroll
    for (int s = 512; s > 0; s >>= 1) {
        if (threadIdx.x < s)
            sk[threadIdx.x] = min(sk[threadIdx.x], sk[threadIdx.x + s]);
        __syncthreads();
    }
    if (threadIdx.x == 0)
        g_bmu_idx = (int)(sk[0] & 0xFFFFFFFFu);
}

// ---------------------------------------------------------------------------
// Pass 2: one block per row (128 threads, one float4 per thread).
// c = rate * influence(row) computed once per block, then
// out = w + c * (x - w). Mirrors JAX op order / weak-typed scalars.
// ---------------------------------------------------------------------------
__global__ __launch_bounds__(128) void som_update_kernel(
    const float* __restrict__ x, const float* __restrict__ w,
    const float* __restrict__ loc, const int* __restrict__ it_p,
    float* __restrict__ out, int has_idx_tail)
{
    __shared__ float s_c;
    const int row = blockIdx.x;

    if (threadIdx.x == 0) {
        const int it = *it_p;
        const double decay   = exp(-(double)it / 2000.0);       // N_ITER
        const float  rate    = (float)(0.5 * decay);            // ALPHA * decay
        const double sigma_t = 128.0 * decay;                   // SIGMA * decay
        const float  inv2s2  = (float)(1.0 / (2.0 * sigma_t * sigma_t));

        const int bidx = g_bmu_idx;
        const float b0 = loc[2 * bidx],     b1 = loc[2 * bidx + 1];
        const float l0 = loc[2 * row],      l1 = loc[2 * row + 1];
        const float d0 = b0 - l0 + 1e-6f;
        const float d1 = b1 - l1 + 1e-6f;
        const float s  = d0 * d0 + d1 * d1;
        const float ld = sqrtf(s);                 // match sqrt-then-square
        const float infl = expf(-(ld * ld) * inv2s2);
        s_c = rate * infl;

        if (row == 0 && has_idx_tail)
            out[(size_t)SOM_MN * SOM_DIM] = (float)bidx;
    }
    __syncthreads();

    const float c = s_c;
    const int t = threadIdx.x;
    const float4* __restrict__ wr = (const float4*)(w + (size_t)row * SOM_DIM);
    const float4* __restrict__ xr = (const float4*)x;
    float4* __restrict__ orow = (float4*)(out + (size_t)row * SOM_DIM);

    float4 wv = wr[t];
    float4 xv = __ldg(&xr[t]);
    float4 o;
    o.x = wv.x + c * (xv.x - wv.x);
    o.y = wv.y + c * (xv.y - wv.y);
    o.z = wv.z + c * (xv.z - wv.z);
    o.w = wv.w + c * (xv.w - wv.w);
    orow[t] = o;
}

extern "C" void kernel_launch(void* const* d_in, const int* in_sizes, int n_in,
                              void* d_out, int out_size)
{
    const float* x   = (const float*)d_in[0];   // (512,)
    const float* w   = (const float*)d_in[1];   // (65536, 512)
    const float* loc = (const float*)d_in[2];   // (65536, 2)
    const int*   it  = (const int*)d_in[3];     // scalar
    float* out = (float*)d_out;

    const int has_tail = (out_size > SOM_MN * SOM_DIM) ? 1 : 0;

    som_dist_kernel<<<N_BLOCKS_P1, 256>>>(x, w);
    som_reduce_kernel<<<1, 1024>>>();
    som_update_kernel<<<SOM_MN, 128>>>(x, w, loc, it, out, has_tail);
}

// round 2
// speedup vs baseline: 2.6922x; 2.6922x over previous
#include <cuda_runtime.h>
#include <math.h>

#define SOM_DIM   512
#define SOM_MN    65536          // 256*256 rows
#define ROWS_PER_BLK 8           // 8 warps per block, one row per warp
#define N_BLOCKS (SOM_MN / ROWS_PER_BLK)   // 8192

__device__ unsigned long long g_partial[N_BLOCKS];
__device__ int   g_bmu_idx;
__device__ float g_rate;
__device__ float g_inv2s2;
__device__ float g_b0;
__device__ float g_b1;

// ---------------------------------------------------------------------------
// Pass 1: per-row squared distance (argmin of sqrt == argmin of sum since
// sqrt monotonic). One warp per row; 4x float4 loads per lane, coalesced.
// Packed (dist_bits<<32 | row) min per block -> g_partial[block].
// ---------------------------------------------------------------------------
__global__ __launch_bounds__(256) void som_dist_kernel(
    const float* __restrict__ x, const float* __restrict__ w)
{
    __shared__ unsigned long long s_keys[ROWS_PER_BLK];
    const int lane = threadIdx.x & 31;
    const int warp = threadIdx.x >> 5;
    const int row  = blockIdx.x * ROWS_PER_BLK + warp;

    const float4* __restrict__ wr = (const float4*)(w + (size_t)row * SOM_DIM);
    const float4* __restrict__ xr = (const float4*)x;

    float acc = 0.0f;
#pragma unroll
    for (int i = 0; i < 4; i++) {
        const int idx = lane + i * 32;            // 128 float4 per row
        float4 wv = wr[idx];
        float4 xv = __ldg(&xr[idx]);
        float d0 = xv.x - wv.x + 1e-6f;
        float d1 = xv.y - wv.y + 1e-6f;
        float d2 = xv.z - wv.z + 1e-6f;
        float d3 = xv.w - wv.w + 1e-6f;
        acc += d0*d0 + d1*d1 + d2*d2 + d3*d3;
    }
#pragma unroll
    for (int o = 16; o > 0; o >>= 1)
        acc += __shfl_xor_sync(0xFFFFFFFFu, acc, o);

    if (lane == 0) {
        // acc >= 0 so fp32 bit pattern is order-preserving as uint.
        unsigned long long key =
            ((unsigned long long)__float_as_uint(acc) << 32) | (unsigned)row;
        s_keys[warp] = key;
    }
    __syncthreads();
    if (threadIdx.x == 0) {
        unsigned long long k = s_keys[0];
#pragma unroll
        for (int i = 1; i < ROWS_PER_BLK; i++)
            k = min(k, s_keys[i]);
        g_partial[blockIdx.x] = k;
    }
}

// ---------------------------------------------------------------------------
// Pass 1b: deterministic reduction of 8192 partial keys -> g_bmu_idx,
// plus all scalar precomputation (the only FP64 in the pipeline) and the
// optional bmu-index tail write.
// ---------------------------------------------------------------------------
__global__ __launch_bounds__(1024) void som_reduce_kernel(
    const float* __restrict__ loc, const int* __restrict__ it_p,
    float* __restrict__ out, int has_idx_tail)
{
    __shared__ unsigned long long sk[1024];
    // 8 independent loads up-front (MLP=8) then reduce.
    unsigned long long v[8];
#pragma unroll
    for (int i = 0; i < 8; i++)
        v[i] = g_partial[threadIdx.x + i * 1024];
    unsigned long long k = v[0];
#pragma unroll
    for (int i = 1; i < 8; i++) k = min(k, v[i]);
    sk[threadIdx.x] = k;
    __syncthreads();
#pragma unroll
    for (int s = 512; s > 0; s >>= 1) {
        if (threadIdx.x < s)
            sk[threadIdx.x] = min(sk[threadIdx.x], sk[threadIdx.x + s]);
        __syncthreads();
    }
    if (threadIdx.x == 0) {
        const int bidx = (int)(sk[0] & 0xFFFFFFFFu);
        g_bmu_idx = bidx;

        const int it = *it_p;
        const double decay   = exp(-(double)it / 2000.0);   // N_ITER
        const double sigma_t = 128.0 * decay;               // SIGMA * decay
        g_rate   = (float)(0.5 * decay);                    // ALPHA * decay
        g_inv2s2 = (float)(1.0 / (2.0 * sigma_t * sigma_t));
        g_b0 = loc[2 * bidx];
        g_b1 = loc[2 * bidx + 1];

        if (has_idx_tail)
            out[(size_t)SOM_MN * SOM_DIM] = (float)bidx;
    }
}

// ---------------------------------------------------------------------------
// Pass 2: warp-per-row, 4 float4 per lane, no syncthreads, no FP64.
// Rows processed in DESCENDING order so the L2-resident tail of W (left
// there by pass 1) is consumed before it gets evicted. __ldcs/__stcs keep
// the streaming data from thrashing L2.
// ---------------------------------------------------------------------------
__global__ __launch_bounds__(256) void som_update_kernel(
    const float* __restrict__ x, const float* __restrict__ w,
    const float* __restrict__ loc, float* __restrict__ out)
{
    const int lane = threadIdx.x & 31;
    const int warp = threadIdx.x >> 5;
    const int row  = (SOM_MN - 1) - (blockIdx.x * ROWS_PER_BLK + warp);

    const float4* __restrict__ wr = (const float4*)(w + (size_t)row * SOM_DIM);
    const float4* __restrict__ xr = (const float4*)x;
    float4* __restrict__ orow = (float4*)(out + (size_t)row * SOM_DIM);

    // Issue all memory first (8 independent loads -> MLP hides everything).
    float4 wv[4], xv[4];
#pragma unroll
    for (int i = 0; i < 4; i++) {
        wv[i] = __ldcs(&wr[lane + 32 * i]);
        xv[i] = __ldg(&xr[lane + 32 * i]);
    }

    // Per-row coefficient (cheap fp32, MUFU), computed redundantly per lane;
    // loc loads are warp-uniform broadcasts, scalar globals are L1 hits.
    const float l0 = __ldg(&loc[2 * row]);
    const float l1 = __ldg(&loc[2 * row + 1]);
    const float d0 = g_b0 - l0 + 1e-6f;
    const float d1 = g_b1 - l1 + 1e-6f;
    const float ld = sqrtf(d0 * d0 + d1 * d1);      // match sqrt-then-square
    const float c  = g_rate * expf(-(ld * ld) * g_inv2s2);

#pragma unroll
    for (int i = 0; i < 4; i++) {
        float4 o;
        o.x = wv[i].x + c * (xv[i].x - wv[i].x);
        o.y = wv[i].y + c * (xv[i].y - wv[i].y);
        o.z = wv[i].z + c * (xv[i].z - wv[i].z);
        o.w = wv[i].w + c * (xv[i].w - wv[i].w);
        __stcs(&orow[lane + 32 * i], o);
    }
}

extern "C" void kernel_launch(void* const* d_in, const int* in_sizes, int n_in,
                              void* d_out, int out_size)
{
    const float* x   = (const float*)d_in[0];   // (512,)
    const float* w   = (const float*)d_in[1];   // (65536, 512)
    const float* loc = (const float*)d_in[2];   // (65536, 2)
    const int*   it  = (const int*)d_in[3];     // scalar
    float* out = (float*)d_out;

    const int has_tail = (out_size > SOM_MN * SOM_DIM) ? 1 : 0;

    som_dist_kernel<<<N_BLOCKS, 256>>>(x, w);
    som_reduce_kernel<<<1, 1024>>>(loc, it, out, has_tail);
    som_update_kernel<<<N_BLOCKS, 256>>>(x, w, loc, out);
}